// round 13
// baseline (speedup 1.0000x reference)
#include <cuda_runtime.h>

// iSWAP(t) on qubits (3,7) of a 16-qubit state, batch 256.
// state: [DIM=65536, BATCH=256] f32 planes (real, imag). out: [2, DIM, BATCH].
// qubit 3 -> bit 12 (weight 4096), qubit 7 -> bit 8 (weight 256).
//
//   out_re = c*x + s*y_p ;  out_im = c*y - s*x_p   (p = partner row, row ^ 4352)
//
// R12: persistent grid-stride single-wave launch (1184 blocks = 148 SMs x 8),
// each thread loops ~10 sequential chunks. Removes ~10 block-waves of
// launch/drain overhead, hoists sincosf + t load out of the loop, and lets
// iteration i+1 loads overlap iteration i store drain. Row mapping and
// streaming hints identical to measured-best R10.

#define F4_PER_ROW 64            // 256 floats / 4
#define DIM_Q 65536
#define PLANE_F4 (DIM_Q * F4_PER_ROW)   // 4194304 float4 per plane
#define XOR_MASK 4352            // (1<<12) | (1<<8)

#define NUM_EQ_ROWS 32768        // rows with b12 == b8
#define NUM_PAIRS   16384        // rows with (b12,b8) = (0,1)
#define TOTAL_VROWS (NUM_EQ_ROWS + NUM_PAIRS)  // 49152
#define TOTAL_WORK  (TOTAL_VROWS * F4_PER_ROW) // 3,145,728 float4-tasks

#define GRID_BLOCKS 1184         // 148 SMs * 8 resident blocks
#define BLOCK_THREADS 256

__global__ __launch_bounds__(BLOCK_THREADS)
void iswap_kernel(const float4* __restrict__ re,
                  const float4* __restrict__ im,
                  const float*  __restrict__ t,
                  float4* __restrict__ out)
{
    float4* __restrict__ out_re = out;
    float4* __restrict__ out_im = out + PLANE_F4;

    float s, c;
    sincosf(t[0], &s, &c);

    const int stride = GRID_BLOCKS * BLOCK_THREADS;     // 303,104

    for (int gid = blockIdx.x * BLOCK_THREADS + threadIdx.x;
         gid < TOTAL_WORK; gid += stride)
    {
        const int col = gid & 63;        // float4 column within row
        const int v   = gid >> 6;        // virtual row id, 0..49151

        if (v < NUM_EQ_ROWS) {
            // ---- identity rows: b12 == b8 == e ----
            const int e    = (v >> 14) & 1;
            const int rest = v & 16383;           // 14 free bits
            const int h    = rest >> 11;          // bits 15:13
            const int m    = (rest >> 8) & 7;     // bits 11:9
            const int l    = rest & 255;          // bits 7:0
            const int row  = (h << 13) | (e << 12) | (m << 9) | (e << 8) | l;
            const int idx  = row * F4_PER_ROW + col;
            const float4 r0 = __ldcs(&re[idx]);
            const float4 i0 = __ldcs(&im[idx]);
            __stcs(&out_re[idx], r0);
            __stcs(&out_im[idx], i0);
        } else {
            // ---- mixed pair: row01 has (b12,b8)=(0,1); partner = row01 ^ 4352 ----
            const int p = v - NUM_EQ_ROWS;        // 14 free bits
            const int h = p >> 11;
            const int m = (p >> 8) & 7;
            const int l = p & 255;
            const int row01 = (h << 13) | (m << 9) | (1 << 8) | l;
            const int row10 = row01 ^ XOR_MASK;
            const int i01 = row01 * F4_PER_ROW + col;
            const int i10 = row10 * F4_PER_ROW + col;

            const float4 x01 = __ldcs(&re[i01]);
            const float4 y01 = __ldcs(&im[i01]);
            const float4 x10 = __ldcs(&re[i10]);
            const float4 y10 = __ldcs(&im[i10]);

            float4 o01r, o01i, o10r, o10i;
            o01r.x = fmaf(c, x01.x,  s * y10.x);
            o01r.y = fmaf(c, x01.y,  s * y10.y);
            o01r.z = fmaf(c, x01.z,  s * y10.z);
            o01r.w = fmaf(c, x01.w,  s * y10.w);

            o01i.x = fmaf(c, y01.x, -s * x10.x);
            o01i.y = fmaf(c, y01.y, -s * x10.y);
            o01i.z = fmaf(c, y01.z, -s * x10.z);
            o01i.w = fmaf(c, y01.w, -s * x10.w);

            o10r.x = fmaf(c, x10.x,  s * y01.x);
            o10r.y = fmaf(c, x10.y,  s * y01.y);
            o10r.z = fmaf(c, x10.z,  s * y01.z);
            o10r.w = fmaf(c, x10.w,  s * y01.w);

            o10i.x = fmaf(c, y10.x, -s * x01.x);
            o10i.y = fmaf(c, y10.y, -s * x01.y);
            o10i.z = fmaf(c, y10.z, -s * x01.z);
            o10i.w = fmaf(c, y10.w, -s * x01.w);

            __stcs(&out_re[i01], o01r);
            __stcs(&out_im[i01], o01i);
            __stcs(&out_re[i10], o10r);
            __stcs(&out_im[i10], o10i);
        }
    }
}

extern "C" void kernel_launch(void* const* d_in, const int* in_sizes, int n_in,
                              void* d_out, int out_size)
{
    const float4* re = (const float4*)d_in[0];
    const float4* im = (const float4*)d_in[1];
    const float*  t  = (const float*)d_in[2];
    float4* out = (float4*)d_out;

    iswap_kernel<<<GRID_BLOCKS, BLOCK_THREADS>>>(re, im, t, out);
    (void)in_sizes; (void)n_in; (void)out_size;
}

// round 14
// speedup vs baseline: 1.0567x; 1.0567x over previous
#include <cuda_runtime.h>

// iSWAP(t) on qubits (3,7) of a 16-qubit state, batch 256.
// state: [DIM=65536, BATCH=256] f32 planes (real, imag). out: [2, DIM, BATCH].
// qubit 3 -> bit 12 (weight 4096), qubit 7 -> bit 8 (weight 256).
//
//   out_re = c*x + s*y_p ;  out_im = c*y - s*x_p   (p = partner row, row ^ 4352)
//
// R13 FINAL (= R10, measured best: kernel 36.5us, 74.6% DRAM, dur 44.4us):
// 1 float4/thread, 12288 blocks, 31 regs, 77% occupancy, streaming hints.
// Session evidence: every deviation (MLP8 tiling R7, interleave R11,
// persistent grid R12) regressed; 268MB logical traffic at ~36.3us is
// ~7.4TB/s aggregate == the B300 balanced-stream HW ceiling. Frozen here.

#define F4_PER_ROW 64            // 256 floats / 4
#define DIM_Q 65536
#define PLANE_F4 (DIM_Q * F4_PER_ROW)   // 4194304 float4 per plane
#define XOR_MASK 4352            // (1<<12) | (1<<8)

#define NUM_EQ_ROWS 32768        // rows with b12 == b8
#define NUM_PAIRS   16384        // rows with (b12,b8) = (0,1)
#define TOTAL_VROWS (NUM_EQ_ROWS + NUM_PAIRS)  // 49152

__global__ __launch_bounds__(256)
void iswap_kernel(const float4* __restrict__ re,
                  const float4* __restrict__ im,
                  const float*  __restrict__ t,
                  float4* __restrict__ out)
{
    const int gid = blockIdx.x * blockDim.x + threadIdx.x;
    const int col = gid & 63;        // float4 column within row
    const int v   = gid >> 6;        // virtual row id, 0..49151

    float4* __restrict__ out_re = out;
    float4* __restrict__ out_im = out + PLANE_F4;

    if (v < NUM_EQ_ROWS) {
        // ---- identity rows: b12 == b8 == e ----
        const int e    = (v >> 14) & 1;
        const int rest = v & 16383;           // 14 free bits
        const int h    = rest >> 11;          // bits 15:13
        const int m    = (rest >> 8) & 7;     // bits 11:9
        const int l    = rest & 255;          // bits 7:0
        const int row  = (h << 13) | (e << 12) | (m << 9) | (e << 8) | l;
        const int idx  = row * F4_PER_ROW + col;
        const float4 r0 = __ldcs(&re[idx]);
        const float4 i0 = __ldcs(&im[idx]);
        __stcs(&out_re[idx], r0);
        __stcs(&out_im[idx], i0);
    } else {
        // ---- mixed pair: row01 has (b12,b8)=(0,1); partner = row01 ^ 4352 ----
        const int p = v - NUM_EQ_ROWS;        // 14 free bits
        const int h = p >> 11;
        const int m = (p >> 8) & 7;
        const int l = p & 255;
        const int row01 = (h << 13) | (m << 9) | (1 << 8) | l;
        const int row10 = row01 ^ XOR_MASK;
        const int i01 = row01 * F4_PER_ROW + col;
        const int i10 = row10 * F4_PER_ROW + col;

        float s, c;
        sincosf(t[0], &s, &c);

        const float4 x01 = __ldcs(&re[i01]);
        const float4 y01 = __ldcs(&im[i01]);
        const float4 x10 = __ldcs(&re[i10]);
        const float4 y10 = __ldcs(&im[i10]);

        float4 o01r, o01i, o10r, o10i;
        o01r.x = fmaf(c, x01.x,  s * y10.x);
        o01r.y = fmaf(c, x01.y,  s * y10.y);
        o01r.z = fmaf(c, x01.z,  s * y10.z);
        o01r.w = fmaf(c, x01.w,  s * y10.w);

        o01i.x = fmaf(c, y01.x, -s * x10.x);
        o01i.y = fmaf(c, y01.y, -s * x10.y);
        o01i.z = fmaf(c, y01.z, -s * x10.z);
        o01i.w = fmaf(c, y01.w, -s * x10.w);

        o10r.x = fmaf(c, x10.x,  s * y01.x);
        o10r.y = fmaf(c, x10.y,  s * y01.y);
        o10r.z = fmaf(c, x10.z,  s * y01.z);
        o10r.w = fmaf(c, x10.w,  s * y01.w);

        o10i.x = fmaf(c, y10.x, -s * x01.x);
        o10i.y = fmaf(c, y10.y, -s * x01.y);
        o10i.z = fmaf(c, y10.z, -s * x01.z);
        o10i.w = fmaf(c, y10.w, -s * x01.w);

        __stcs(&out_re[i01], o01r);
        __stcs(&out_im[i01], o01i);
        __stcs(&out_re[i10], o10r);
        __stcs(&out_im[i10], o10i);
    }
}

extern "C" void kernel_launch(void* const* d_in, const int* in_sizes, int n_in,
                              void* d_out, int out_size)
{
    const float4* re = (const float4*)d_in[0];
    const float4* im = (const float4*)d_in[1];
    const float*  t  = (const float*)d_in[2];
    float4* out = (float4*)d_out;

    const int total_threads = TOTAL_VROWS * F4_PER_ROW;  // 3,145,728
    const int block = 256;
    const int grid  = total_threads / block;             // 12,288
    iswap_kernel<<<grid, block>>>(re, im, t, out);
    (void)in_sizes; (void)n_in; (void)out_size;
}